// round 3
// baseline (speedup 1.0000x reference)
#include <cuda_runtime.h>

#define D 16
#define NMAX 100000
#define EMAX 3400000

// Scratch (static __device__ — no allocation allowed).
// NOTE: these must only be referenced from DEVICE code (host-side symbol
// addresses are invalid — that was the Round-2 bug).
__device__ float4 g_fs[NMAX * 4];     // feat_src  [N,16]
__device__ float4 g_fd[NMAX * 4];     // feat_dst  [N,16]
__device__ float4 g_h2[NMAX * 4];     // layer-1 output / layer-2 input
__device__ int    g_cnt[NMAX];        // per-dst edge count
__device__ int    g_ptr[NMAX + 1];    // CSR row pointers
__device__ int    g_cur[NMAX];        // scatter cursors
__device__ int    g_esrc[EMAX];       // src index sorted by dst

// ---------------------------------------------------------------------------
// feat kernel: out = h@W + b  (which_out: 0 -> g_fs, 1 -> g_fd)
// zero_cnt=1 additionally zeroes the histogram counters.
// ---------------------------------------------------------------------------
__global__ __launch_bounds__(256) void feat_kernel(
        const float* __restrict__ h, int use_h2,
        const float* __restrict__ W, const float* __restrict__ b,
        int which_out, int zero_cnt, int N) {
    __shared__ float sW[D * D], sb[D];
    int tid = threadIdx.x;
    if (tid < D * D) sW[tid] = W[tid];
    if (tid < D)     sb[tid] = b[tid];
    __syncthreads();

    int n = blockIdx.x * blockDim.x + tid;
    if (n >= N) return;

    const float4* h4 = use_h2 ? (g_h2 + n * 4) : ((const float4*)h + n * 4);
    float hr[D];
#pragma unroll
    for (int i = 0; i < 4; i++) {
        float4 v = h4[i];
        hr[4 * i + 0] = v.x; hr[4 * i + 1] = v.y; hr[4 * i + 2] = v.z; hr[4 * i + 3] = v.w;
    }
    float o[D];
#pragma unroll
    for (int j = 0; j < D; j++) o[j] = sb[j];
#pragma unroll
    for (int k = 0; k < D; k++) {
        float hv = hr[k];
#pragma unroll
        for (int j = 0; j < D; j++) o[j] = fmaf(hv, sW[k * D + j], o[j]);
    }
    float4* outbuf = which_out ? g_fd : g_fs;   // device-side symbol reference
#pragma unroll
    for (int i = 0; i < 4; i++)
        outbuf[n * 4 + i] = make_float4(o[4 * i], o[4 * i + 1], o[4 * i + 2], o[4 * i + 3]);
    if (zero_cnt) g_cnt[n] = 0;
}

// ---------------------------------------------------------------------------
// CSR build: histogram -> scan -> scatter
// ---------------------------------------------------------------------------
__global__ void hist_kernel(const int* __restrict__ dst, int E) {
    int e = blockIdx.x * blockDim.x + threadIdx.x;
    if (e < E) atomicAdd(&g_cnt[dst[e]], 1);
}

__global__ __launch_bounds__(1024) void scan_kernel(int N) {
    __shared__ int sp[1024];
    int tid = threadIdx.x;
    int chunk = (N + 1023) >> 10;
    int s = tid * chunk;
    int e = min(s + chunk, N);
    int sum = 0;
    for (int i = s; i < e; i++) sum += g_cnt[i];
    sp[tid] = sum;
    __syncthreads();
    // Hillis-Steele inclusive scan
    for (int o = 1; o < 1024; o <<= 1) {
        int u = (tid >= o) ? sp[tid - o] : 0;
        __syncthreads();
        sp[tid] += u;
        __syncthreads();
    }
    int off = sp[tid] - sum;  // exclusive
    for (int i = s; i < e; i++) {
        int c = g_cnt[i];
        g_ptr[i] = off;
        g_cur[i] = off;
        off += c;
    }
    if (tid == 1023) g_ptr[N] = off;
}

__global__ void scatter_kernel(const int* __restrict__ src, const int* __restrict__ dst, int E) {
    int e = blockIdx.x * blockDim.x + threadIdx.x;
    if (e >= E) return;
    int pos = atomicAdd(&g_cur[dst[e]], 1);
    g_esrc[pos] = src[e];
}

// ---------------------------------------------------------------------------
// accumulate kernel: one warp per dst node, no atomics.
//   score_e = sum_j lr02(fs[s][j]+fd[t][j])*attn[j]; ex = exp(score)
//   out[t]  = leaky01( (sum ex*fs[s]) / (sum ex) )
// ---------------------------------------------------------------------------
__device__ __forceinline__ float lr02(float x)  { return x > 0.f ? x : 0.2f  * x; }
__device__ __forceinline__ float lr001(float x) { return x > 0.f ? x : 0.01f * x; }

__global__ __launch_bounds__(256) void accum_kernel(
        const float* __restrict__ attn, float* __restrict__ out_ext,
        int to_internal, int N) {
    __shared__ float sat[D];
    if (threadIdx.x < D) sat[threadIdx.x] = attn[threadIdx.x];
    __syncthreads();

    int w = (blockIdx.x * blockDim.x + threadIdx.x) >> 5;
    int lane = threadIdx.x & 31;
    if (w >= N) return;  // warp-uniform

    int beg = g_ptr[w];
    int end = g_ptr[w + 1];

    float4 b0 = g_fd[w * 4 + 0], b1 = g_fd[w * 4 + 1];
    float4 b2 = g_fd[w * 4 + 2], b3 = g_fd[w * 4 + 3];

    float acc[D];
#pragma unroll
    for (int j = 0; j < D; j++) acc[j] = 0.f;
    float den = 0.f;

    for (int i = beg + lane; i < end; i += 32) {
        int s = g_esrc[i];
        float4 a0 = g_fs[s * 4 + 0], a1 = g_fs[s * 4 + 1];
        float4 a2 = g_fs[s * 4 + 2], a3 = g_fs[s * 4 + 3];

        float sc = 0.f;
        sc = fmaf(lr02(a0.x + b0.x), sat[0],  sc);
        sc = fmaf(lr02(a0.y + b0.y), sat[1],  sc);
        sc = fmaf(lr02(a0.z + b0.z), sat[2],  sc);
        sc = fmaf(lr02(a0.w + b0.w), sat[3],  sc);
        sc = fmaf(lr02(a1.x + b1.x), sat[4],  sc);
        sc = fmaf(lr02(a1.y + b1.y), sat[5],  sc);
        sc = fmaf(lr02(a1.z + b1.z), sat[6],  sc);
        sc = fmaf(lr02(a1.w + b1.w), sat[7],  sc);
        sc = fmaf(lr02(a2.x + b2.x), sat[8],  sc);
        sc = fmaf(lr02(a2.y + b2.y), sat[9],  sc);
        sc = fmaf(lr02(a2.z + b2.z), sat[10], sc);
        sc = fmaf(lr02(a2.w + b2.w), sat[11], sc);
        sc = fmaf(lr02(a3.x + b3.x), sat[12], sc);
        sc = fmaf(lr02(a3.y + b3.y), sat[13], sc);
        sc = fmaf(lr02(a3.z + b3.z), sat[14], sc);
        sc = fmaf(lr02(a3.w + b3.w), sat[15], sc);

        float ex = __expf(sc);
        den += ex;
        acc[0]  = fmaf(ex, a0.x, acc[0]);  acc[1]  = fmaf(ex, a0.y, acc[1]);
        acc[2]  = fmaf(ex, a0.z, acc[2]);  acc[3]  = fmaf(ex, a0.w, acc[3]);
        acc[4]  = fmaf(ex, a1.x, acc[4]);  acc[5]  = fmaf(ex, a1.y, acc[5]);
        acc[6]  = fmaf(ex, a1.z, acc[6]);  acc[7]  = fmaf(ex, a1.w, acc[7]);
        acc[8]  = fmaf(ex, a2.x, acc[8]);  acc[9]  = fmaf(ex, a2.y, acc[9]);
        acc[10] = fmaf(ex, a2.z, acc[10]); acc[11] = fmaf(ex, a2.w, acc[11]);
        acc[12] = fmaf(ex, a3.x, acc[12]); acc[13] = fmaf(ex, a3.y, acc[13]);
        acc[14] = fmaf(ex, a3.z, acc[14]); acc[15] = fmaf(ex, a3.w, acc[15]);
    }

    // den: full butterfly
#pragma unroll
    for (int o = 16; o >= 1; o >>= 1) den += __shfl_xor_sync(0xffffffffu, den, o);

    // acc: multi-value exchange reduction. After all steps, even lane L holds
    // component ((L>>1)&15) of the full 32-lane sum in acc[0].
#pragma unroll
    for (int j = 0; j < 8; j++) {
        float send = (lane & 16) ? acc[j] : acc[j + 8];
        float recv = __shfl_xor_sync(0xffffffffu, send, 16);
        acc[j] = ((lane & 16) ? acc[j + 8] : acc[j]) + recv;
    }
#pragma unroll
    for (int j = 0; j < 4; j++) {
        float send = (lane & 8) ? acc[j] : acc[j + 4];
        float recv = __shfl_xor_sync(0xffffffffu, send, 8);
        acc[j] = ((lane & 8) ? acc[j + 4] : acc[j]) + recv;
    }
#pragma unroll
    for (int j = 0; j < 2; j++) {
        float send = (lane & 4) ? acc[j] : acc[j + 2];
        float recv = __shfl_xor_sync(0xffffffffu, send, 4);
        acc[j] = ((lane & 4) ? acc[j + 2] : acc[j]) + recv;
    }
    {
        float send = (lane & 2) ? acc[0] : acc[1];
        float recv = __shfl_xor_sync(0xffffffffu, send, 2);
        acc[0] = ((lane & 2) ? acc[1] : acc[0]) + recv;
    }
    acc[0] += __shfl_xor_sync(0xffffffffu, acc[0], 1);

    float inv = (den > 0.f) ? (1.0f / den) : 0.f;
    float* out = to_internal ? (float*)g_h2 : out_ext;
    if (!(lane & 1)) {
        float v = lr001(acc[0] * inv);
        out[w * D + ((lane >> 1) & 15)] = v;
    }
}

// ---------------------------------------------------------------------------
// launch
// ---------------------------------------------------------------------------
extern "C" void kernel_launch(void* const* d_in, const int* in_sizes, int n_in,
                              void* d_out, int out_size) {
    const float* emb  = (const float*)d_in[0];
    const int*   src1 = (const int*)d_in[1];
    const int*   dst1 = (const int*)d_in[2];
    const int*   src2 = (const int*)d_in[3];
    const int*   dst2 = (const int*)d_in[4];
    const float* Ws1  = (const float*)d_in[5];
    const float* bs1  = (const float*)d_in[6];
    const float* Wd1  = (const float*)d_in[7];
    const float* bd1  = (const float*)d_in[8];
    const float* at1  = (const float*)d_in[9];
    const float* Ws2  = (const float*)d_in[10];
    const float* bs2  = (const float*)d_in[11];
    const float* Wd2  = (const float*)d_in[12];
    const float* bd2  = (const float*)d_in[13];
    const float* at2  = (const float*)d_in[14];

    int N  = in_sizes[0] / D;
    int E1 = in_sizes[1];
    int E2 = in_sizes[3];

    int nbN  = (N + 255) / 256;
    int nbE1 = (E1 + 255) / 256;
    int nbE2 = (E2 + 255) / 256;
    int nbW  = (N + 7) / 8;  // one warp per node, 256-thread blocks

    // ---- Layer 1 ----
    feat_kernel<<<nbN, 256>>>(emb, 0, Ws1, bs1, 0 /*g_fs*/, 1, N);
    feat_kernel<<<nbN, 256>>>(emb, 0, Wd1, bd1, 1 /*g_fd*/, 0, N);
    hist_kernel<<<nbE1, 256>>>(dst1, E1);
    scan_kernel<<<1, 1024>>>(N);
    scatter_kernel<<<nbE1, 256>>>(src1, dst1, E1);
    accum_kernel<<<nbW, 256>>>(at1, nullptr, 1, N);

    // ---- Layer 2 ----
    feat_kernel<<<nbN, 256>>>(nullptr, 1, Ws2, bs2, 0 /*g_fs*/, 1, N);
    feat_kernel<<<nbN, 256>>>(nullptr, 1, Wd2, bd2, 1 /*g_fd*/, 0, N);
    hist_kernel<<<nbE2, 256>>>(dst2, E2);
    scan_kernel<<<1, 1024>>>(N);
    scatter_kernel<<<nbE2, 256>>>(src2, dst2, E2);
    accum_kernel<<<nbW, 256>>>(at2, (float*)d_out, 0, N);
}

// round 4
// speedup vs baseline: 2.2382x; 2.2382x over previous
#include <cuda_runtime.h>
#include <cuda_fp16.h>

#define D 16
#define NMAX 100000
#define EMAX 3400000
#define SCAN_BLK 512

// Scratch (static __device__). Referenced ONLY from device code.
__device__ uint4  g_fsh[NMAX * 2];    // feat_src as fp16: 16 halves = 32B/row
__device__ float4 g_fd[NMAX * 4];     // feat_dst fp32 [N,16]
__device__ float4 g_h2[NMAX * 4];     // layer-1 output / layer-2 input
__device__ int    g_cnt[NMAX];        // per-dst edge count
__device__ int    g_ptr[NMAX + 1];    // CSR row pointers
__device__ int    g_cur[NMAX];        // scatter cursors
__device__ int    g_esrc[EMAX];       // src index sorted by dst
__device__ int    g_bsum[1024];       // block partial sums (scan)
__device__ int    g_boff[1024];       // block offsets (scan)

// ---------------------------------------------------------------------------
// feat kernel: fs = h@Wsrc+bsrc (fp16 out), fd = h@Wdst+bdst (fp32 out)
// Also zeroes the per-node histogram counters.
// ---------------------------------------------------------------------------
__global__ __launch_bounds__(256) void feat_kernel(
        const float* __restrict__ h, int use_h2,
        const float* __restrict__ Wsrc, const float* __restrict__ bsrc,
        const float* __restrict__ Wdst, const float* __restrict__ bdst,
        int N) {
    __shared__ float sWs[D * D], sWd[D * D], sbs[D], sbd[D];
    int tid = threadIdx.x;
    if (tid < D * D) { sWs[tid] = Wsrc[tid]; sWd[tid] = Wdst[tid]; }
    if (tid < D)     { sbs[tid] = bsrc[tid]; sbd[tid] = bdst[tid]; }
    __syncthreads();

    int n = blockIdx.x * blockDim.x + tid;
    if (n >= N) return;

    const float4* h4 = use_h2 ? (g_h2 + n * 4) : ((const float4*)h + n * 4);
    float hr[D];
#pragma unroll
    for (int i = 0; i < 4; i++) {
        float4 v = h4[i];
        hr[4 * i + 0] = v.x; hr[4 * i + 1] = v.y; hr[4 * i + 2] = v.z; hr[4 * i + 3] = v.w;
    }
    float os[D], od[D];
#pragma unroll
    for (int j = 0; j < D; j++) { os[j] = sbs[j]; od[j] = sbd[j]; }
#pragma unroll
    for (int k = 0; k < D; k++) {
        float hv = hr[k];
#pragma unroll
        for (int j = 0; j < D; j++) {
            os[j] = fmaf(hv, sWs[k * D + j], os[j]);
            od[j] = fmaf(hv, sWd[k * D + j], od[j]);
        }
    }
    // fp16 pack of os
    uint4 p0, p1;
    {
        __half2 t;
        t = __floats2half2_rn(os[0],  os[1]);  p0.x = *reinterpret_cast<unsigned*>(&t);
        t = __floats2half2_rn(os[2],  os[3]);  p0.y = *reinterpret_cast<unsigned*>(&t);
        t = __floats2half2_rn(os[4],  os[5]);  p0.z = *reinterpret_cast<unsigned*>(&t);
        t = __floats2half2_rn(os[6],  os[7]);  p0.w = *reinterpret_cast<unsigned*>(&t);
        t = __floats2half2_rn(os[8],  os[9]);  p1.x = *reinterpret_cast<unsigned*>(&t);
        t = __floats2half2_rn(os[10], os[11]); p1.y = *reinterpret_cast<unsigned*>(&t);
        t = __floats2half2_rn(os[12], os[13]); p1.z = *reinterpret_cast<unsigned*>(&t);
        t = __floats2half2_rn(os[14], os[15]); p1.w = *reinterpret_cast<unsigned*>(&t);
    }
    g_fsh[n * 2 + 0] = p0;
    g_fsh[n * 2 + 1] = p1;
#pragma unroll
    for (int i = 0; i < 4; i++)
        g_fd[n * 4 + i] = make_float4(od[4 * i], od[4 * i + 1], od[4 * i + 2], od[4 * i + 3]);
    g_cnt[n] = 0;
}

// ---------------------------------------------------------------------------
// CSR build: histogram -> hierarchical scan -> scatter
// ---------------------------------------------------------------------------
__global__ void hist_kernel(const int* __restrict__ dst, int E) {
    int e = blockIdx.x * blockDim.x + threadIdx.x;
    if (e < E) atomicAdd(&g_cnt[dst[e]], 1);
}

// pass 1: per-block exclusive scan; local result -> g_ptr, block total -> g_bsum
__global__ __launch_bounds__(SCAN_BLK) void scan1_kernel(int N) {
    __shared__ int swarp[SCAN_BLK / 32];
    int tid = threadIdx.x;
    int lane = tid & 31;
    int wid = tid >> 5;
    int i = blockIdx.x * SCAN_BLK + tid;
    int v = (i < N) ? g_cnt[i] : 0;
    int x = v;
#pragma unroll
    for (int o = 1; o < 32; o <<= 1) {
        int y = __shfl_up_sync(0xffffffffu, x, o);
        if (lane >= o) x += y;
    }
    if (lane == 31) swarp[wid] = x;
    __syncthreads();
    if (wid == 0) {
        int s = (lane < SCAN_BLK / 32) ? swarp[lane] : 0;
#pragma unroll
        for (int o = 1; o < SCAN_BLK / 32; o <<= 1) {
            int y = __shfl_up_sync(0xffffffffu, s, o);
            if (lane >= o) s += y;
        }
        if (lane < SCAN_BLK / 32) swarp[lane] = s;  // inclusive warp sums
    }
    __syncthreads();
    int woff = (wid > 0) ? swarp[wid - 1] : 0;
    if (i < N) g_ptr[i] = x - v + woff;              // local exclusive
    if (tid == SCAN_BLK - 1) g_bsum[blockIdx.x] = swarp[SCAN_BLK / 32 - 1];
}

// pass 2: single block scans block sums (NBLK <= 1024 assumed; here ~196)
__global__ __launch_bounds__(256) void scan2_kernel(int NBLK) {
    __shared__ int sp[256];
    int tid = threadIdx.x;
    int v = (tid < NBLK) ? g_bsum[tid] : 0;
    sp[tid] = v;
    __syncthreads();
    for (int o = 1; o < 256; o <<= 1) {
        int u = (tid >= o) ? sp[tid - o] : 0;
        __syncthreads();
        sp[tid] += u;
        __syncthreads();
    }
    if (tid < NBLK) g_boff[tid] = sp[tid] - v;  // exclusive
}

// pass 3: add block offset; init cursors; write g_ptr[N]=E
__global__ __launch_bounds__(SCAN_BLK) void scan3_kernel(int N, int E) {
    int i = blockIdx.x * SCAN_BLK + threadIdx.x;
    if (i < N) {
        int p = g_ptr[i] + g_boff[blockIdx.x];
        g_ptr[i] = p;
        g_cur[i] = p;
    }
    if (i == 0) g_ptr[N] = E;
}

__global__ void scatter_kernel(const int* __restrict__ src, const int* __restrict__ dst, int E) {
    int e = blockIdx.x * blockDim.x + threadIdx.x;
    if (e >= E) return;
    int pos = atomicAdd(&g_cur[dst[e]], 1);
    g_esrc[pos] = src[e];
}

// ---------------------------------------------------------------------------
// accumulate kernel: one warp per dst node, no atomics.
// ---------------------------------------------------------------------------
__device__ __forceinline__ float lr02(float x)  { return x > 0.f ? x : 0.2f  * x; }
__device__ __forceinline__ float lr001(float x) { return x > 0.f ? x : 0.01f * x; }

__global__ __launch_bounds__(256) void accum_kernel(
        const float* __restrict__ attn, float* __restrict__ out_ext,
        int to_internal, int N) {
    __shared__ float sat[D];
    if (threadIdx.x < D) sat[threadIdx.x] = attn[threadIdx.x];
    __syncthreads();

    int w = (blockIdx.x * blockDim.x + threadIdx.x) >> 5;
    int lane = threadIdx.x & 31;
    if (w >= N) return;  // warp-uniform

    int beg = g_ptr[w];
    int end = g_ptr[w + 1];

    float4 b0 = g_fd[w * 4 + 0], b1 = g_fd[w * 4 + 1];
    float4 b2 = g_fd[w * 4 + 2], b3 = g_fd[w * 4 + 3];
    float bb[D] = { b0.x, b0.y, b0.z, b0.w, b1.x, b1.y, b1.z, b1.w,
                    b2.x, b2.y, b2.z, b2.w, b3.x, b3.y, b3.z, b3.w };

    float acc[D];
#pragma unroll
    for (int j = 0; j < D; j++) acc[j] = 0.f;
    float den = 0.f;

    for (int i = beg + lane; i < end; i += 32) {
        int s = g_esrc[i];
        uint4 r0 = g_fsh[s * 2 + 0];
        uint4 r1 = g_fsh[s * 2 + 1];
        float a[D];
        {
            float2 f;
            f = __half22float2(*reinterpret_cast<__half2*>(&r0.x)); a[0]  = f.x; a[1]  = f.y;
            f = __half22float2(*reinterpret_cast<__half2*>(&r0.y)); a[2]  = f.x; a[3]  = f.y;
            f = __half22float2(*reinterpret_cast<__half2*>(&r0.z)); a[4]  = f.x; a[5]  = f.y;
            f = __half22float2(*reinterpret_cast<__half2*>(&r0.w)); a[6]  = f.x; a[7]  = f.y;
            f = __half22float2(*reinterpret_cast<__half2*>(&r1.x)); a[8]  = f.x; a[9]  = f.y;
            f = __half22float2(*reinterpret_cast<__half2*>(&r1.y)); a[10] = f.x; a[11] = f.y;
            f = __half22float2(*reinterpret_cast<__half2*>(&r1.z)); a[12] = f.x; a[13] = f.y;
            f = __half22float2(*reinterpret_cast<__half2*>(&r1.w)); a[14] = f.x; a[15] = f.y;
        }

        float sc = 0.f;
#pragma unroll
        for (int j = 0; j < D; j++) sc = fmaf(lr02(a[j] + bb[j]), sat[j], sc);

        float ex = __expf(sc);
        den += ex;
#pragma unroll
        for (int j = 0; j < D; j++) acc[j] = fmaf(ex, a[j], acc[j]);
    }

    // den: full butterfly
#pragma unroll
    for (int o = 16; o >= 1; o >>= 1) den += __shfl_xor_sync(0xffffffffu, den, o);

    // acc: multi-value exchange reduction. After all steps, even lane L holds
    // component ((L>>1)&15) of the full 32-lane sum in acc[0].
#pragma unroll
    for (int j = 0; j < 8; j++) {
        float send = (lane & 16) ? acc[j] : acc[j + 8];
        float recv = __shfl_xor_sync(0xffffffffu, send, 16);
        acc[j] = ((lane & 16) ? acc[j + 8] : acc[j]) + recv;
    }
#pragma unroll
    for (int j = 0; j < 4; j++) {
        float send = (lane & 8) ? acc[j] : acc[j + 4];
        float recv = __shfl_xor_sync(0xffffffffu, send, 8);
        acc[j] = ((lane & 8) ? acc[j + 4] : acc[j]) + recv;
    }
#pragma unroll
    for (int j = 0; j < 2; j++) {
        float send = (lane & 4) ? acc[j] : acc[j + 2];
        float recv = __shfl_xor_sync(0xffffffffu, send, 4);
        acc[j] = ((lane & 4) ? acc[j + 2] : acc[j]) + recv;
    }
    {
        float send = (lane & 2) ? acc[0] : acc[1];
        float recv = __shfl_xor_sync(0xffffffffu, send, 2);
        acc[0] = ((lane & 2) ? acc[1] : acc[0]) + recv;
    }
    acc[0] += __shfl_xor_sync(0xffffffffu, acc[0], 1);

    float inv = (den > 0.f) ? (1.0f / den) : 0.f;
    float* out = to_internal ? (float*)g_h2 : out_ext;
    if (!(lane & 1)) {
        float v = lr001(acc[0] * inv);
        out[w * D + ((lane >> 1) & 15)] = v;
    }
}

// ---------------------------------------------------------------------------
// launch
// ---------------------------------------------------------------------------
extern "C" void kernel_launch(void* const* d_in, const int* in_sizes, int n_in,
                              void* d_out, int out_size) {
    const float* emb  = (const float*)d_in[0];
    const int*   src1 = (const int*)d_in[1];
    const int*   dst1 = (const int*)d_in[2];
    const int*   src2 = (const int*)d_in[3];
    const int*   dst2 = (const int*)d_in[4];
    const float* Ws1  = (const float*)d_in[5];
    const float* bs1  = (const float*)d_in[6];
    const float* Wd1  = (const float*)d_in[7];
    const float* bd1  = (const float*)d_in[8];
    const float* at1  = (const float*)d_in[9];
    const float* Ws2  = (const float*)d_in[10];
    const float* bs2  = (const float*)d_in[11];
    const float* Wd2  = (const float*)d_in[12];
    const float* bd2  = (const float*)d_in[13];
    const float* at2  = (const float*)d_in[14];

    int N  = in_sizes[0] / D;
    int E1 = in_sizes[1];
    int E2 = in_sizes[3];

    int nbN  = (N + 255) / 256;
    int nbE1 = (E1 + 255) / 256;
    int nbE2 = (E2 + 255) / 256;
    int nbW  = (N + 7) / 8;                    // one warp per node
    int nbS  = (N + SCAN_BLK - 1) / SCAN_BLK;  // scan blocks (~196)

    // ---- Layer 1 ----
    feat_kernel<<<nbN, 256>>>(emb, 0, Ws1, bs1, Wd1, bd1, N);
    hist_kernel<<<nbE1, 256>>>(dst1, E1);
    scan1_kernel<<<nbS, SCAN_BLK>>>(N);
    scan2_kernel<<<1, 256>>>(nbS);
    scan3_kernel<<<nbS, SCAN_BLK>>>(N, E1);
    scatter_kernel<<<nbE1, 256>>>(src1, dst1, E1);
    accum_kernel<<<nbW, 256>>>(at1, nullptr, 1, N);

    // ---- Layer 2 ----
    feat_kernel<<<nbN, 256>>>(nullptr, 1, Ws2, bs2, Wd2, bd2, N);
    hist_kernel<<<nbE2, 256>>>(dst2, E2);
    scan1_kernel<<<nbS, SCAN_BLK>>>(N);
    scan2_kernel<<<1, 256>>>(nbS);
    scan3_kernel<<<nbS, SCAN_BLK>>>(N, E2);
    scatter_kernel<<<nbE2, 256>>>(src2, dst2, E2);
    accum_kernel<<<nbW, 256>>>(at2, (float*)d_out, 0, N);
}

// round 5
// speedup vs baseline: 2.3809x; 1.0637x over previous
#include <cuda_runtime.h>
#include <cuda_fp16.h>

#define D 16
#define NMAX 100000
#define EMAX 3400000
#define SCAN_BLK 512

// Scratch (static __device__). Referenced ONLY from device code.
__device__ uint4  g_fsh[NMAX * 2];    // feat_src as fp16: 16 halves = 32B/row
__device__ float4 g_fd[NMAX * 4];     // feat_dst fp32 [N,16]
__device__ float4 g_h2[NMAX * 4];     // layer-1 output / layer-2 input
__device__ int    g_cnt[NMAX];        // per-dst edge count
__device__ int    g_ptr[NMAX + 1];    // CSR row pointers
__device__ int    g_rank[EMAX];       // per-edge rank within dst bucket
__device__ int    g_esrc[EMAX];       // src index sorted by dst
__device__ int    g_bsum[1024];       // block partial sums (scan)
__device__ int    g_boff[1024];       // block offsets (scan)

// ---------------------------------------------------------------------------
// feat kernel: fs = h@Wsrc+bsrc (fp16 out), fd = h@Wdst+bdst (fp32 out)
// Also zeroes the per-node histogram counters.
// ---------------------------------------------------------------------------
__global__ __launch_bounds__(256) void feat_kernel(
        const float* __restrict__ h, int use_h2,
        const float* __restrict__ Wsrc, const float* __restrict__ bsrc,
        const float* __restrict__ Wdst, const float* __restrict__ bdst,
        int N) {
    __shared__ float sWs[D * D], sWd[D * D], sbs[D], sbd[D];
    int tid = threadIdx.x;
    if (tid < D * D) { sWs[tid] = Wsrc[tid]; sWd[tid] = Wdst[tid]; }
    if (tid < D)     { sbs[tid] = bsrc[tid]; sbd[tid] = bdst[tid]; }
    __syncthreads();

    int n = blockIdx.x * blockDim.x + tid;
    if (n >= N) return;

    const float4* h4 = use_h2 ? (g_h2 + n * 4) : ((const float4*)h + n * 4);
    float hr[D];
#pragma unroll
    for (int i = 0; i < 4; i++) {
        float4 v = h4[i];
        hr[4 * i + 0] = v.x; hr[4 * i + 1] = v.y; hr[4 * i + 2] = v.z; hr[4 * i + 3] = v.w;
    }
    float os[D], od[D];
#pragma unroll
    for (int j = 0; j < D; j++) { os[j] = sbs[j]; od[j] = sbd[j]; }
#pragma unroll
    for (int k = 0; k < D; k++) {
        float hv = hr[k];
#pragma unroll
        for (int j = 0; j < D; j++) {
            os[j] = fmaf(hv, sWs[k * D + j], os[j]);
            od[j] = fmaf(hv, sWd[k * D + j], od[j]);
        }
    }
    uint4 p0, p1;
    {
        __half2 t;
        t = __floats2half2_rn(os[0],  os[1]);  p0.x = *reinterpret_cast<unsigned*>(&t);
        t = __floats2half2_rn(os[2],  os[3]);  p0.y = *reinterpret_cast<unsigned*>(&t);
        t = __floats2half2_rn(os[4],  os[5]);  p0.z = *reinterpret_cast<unsigned*>(&t);
        t = __floats2half2_rn(os[6],  os[7]);  p0.w = *reinterpret_cast<unsigned*>(&t);
        t = __floats2half2_rn(os[8],  os[9]);  p1.x = *reinterpret_cast<unsigned*>(&t);
        t = __floats2half2_rn(os[10], os[11]); p1.y = *reinterpret_cast<unsigned*>(&t);
        t = __floats2half2_rn(os[12], os[13]); p1.z = *reinterpret_cast<unsigned*>(&t);
        t = __floats2half2_rn(os[14], os[15]); p1.w = *reinterpret_cast<unsigned*>(&t);
    }
    g_fsh[n * 2 + 0] = p0;
    g_fsh[n * 2 + 1] = p1;
#pragma unroll
    for (int i = 0; i < 4; i++)
        g_fd[n * 4 + i] = make_float4(od[4 * i], od[4 * i + 1], od[4 * i + 2], od[4 * i + 3]);
    g_cnt[n] = 0;
}

// ---------------------------------------------------------------------------
// CSR build: rank(hist) -> hierarchical scan -> scatter
// ---------------------------------------------------------------------------
// hist + per-edge rank via atomic return; 4 edges/thread vectorized
__global__ __launch_bounds__(256) void rank_kernel(const int* __restrict__ dst, int E) {
    int i = blockIdx.x * blockDim.x + threadIdx.x;
    int e = i * 4;
    if (e + 3 < E) {
        int4 d = reinterpret_cast<const int4*>(dst)[i];
        int4 r;
        r.x = atomicAdd(&g_cnt[d.x], 1);
        r.y = atomicAdd(&g_cnt[d.y], 1);
        r.z = atomicAdd(&g_cnt[d.z], 1);
        r.w = atomicAdd(&g_cnt[d.w], 1);
        reinterpret_cast<int4*>(g_rank)[i] = r;
    } else {
        for (; e < E; e++) g_rank[e] = atomicAdd(&g_cnt[dst[e]], 1);
    }
}

// pass 1: per-block exclusive scan; local result -> g_ptr, block total -> g_bsum
__global__ __launch_bounds__(SCAN_BLK) void scan1_kernel(int N) {
    __shared__ int swarp[SCAN_BLK / 32];
    int tid = threadIdx.x;
    int lane = tid & 31;
    int wid = tid >> 5;
    int i = blockIdx.x * SCAN_BLK + tid;
    int v = (i < N) ? g_cnt[i] : 0;
    int x = v;
#pragma unroll
    for (int o = 1; o < 32; o <<= 1) {
        int y = __shfl_up_sync(0xffffffffu, x, o);
        if (lane >= o) x += y;
    }
    if (lane == 31) swarp[wid] = x;
    __syncthreads();
    if (wid == 0) {
        int s = (lane < SCAN_BLK / 32) ? swarp[lane] : 0;
#pragma unroll
        for (int o = 1; o < SCAN_BLK / 32; o <<= 1) {
            int y = __shfl_up_sync(0xffffffffu, s, o);
            if (lane >= o) s += y;
        }
        if (lane < SCAN_BLK / 32) swarp[lane] = s;
    }
    __syncthreads();
    int woff = (wid > 0) ? swarp[wid - 1] : 0;
    if (i < N) g_ptr[i] = x - v + woff;
    if (tid == SCAN_BLK - 1) g_bsum[blockIdx.x] = swarp[SCAN_BLK / 32 - 1];
}

// pass 2: single block scans block sums (NBLK <= 256)
__global__ __launch_bounds__(256) void scan2_kernel(int NBLK) {
    __shared__ int sp[256];
    int tid = threadIdx.x;
    int v = (tid < NBLK) ? g_bsum[tid] : 0;
    sp[tid] = v;
    __syncthreads();
    for (int o = 1; o < 256; o <<= 1) {
        int u = (tid >= o) ? sp[tid - o] : 0;
        __syncthreads();
        sp[tid] += u;
        __syncthreads();
    }
    if (tid < NBLK) g_boff[tid] = sp[tid] - v;
}

// pass 3: add block offset; write g_ptr[N]=E
__global__ __launch_bounds__(SCAN_BLK) void scan3_kernel(int N, int E) {
    int i = blockIdx.x * SCAN_BLK + threadIdx.x;
    if (i < N) g_ptr[i] += g_boff[blockIdx.x];
    if (i == 0) g_ptr[N] = E;
}

// scatter: pos = ptr[dst] + rank (no atomics); 4 edges/thread vectorized
__global__ __launch_bounds__(256) void scatter_kernel(
        const int* __restrict__ src, const int* __restrict__ dst, int E) {
    int i = blockIdx.x * blockDim.x + threadIdx.x;
    int e = i * 4;
    if (e + 3 < E) {
        int4 s = reinterpret_cast<const int4*>(src)[i];
        int4 d = reinterpret_cast<const int4*>(dst)[i];
        int4 r = reinterpret_cast<const int4*>(g_rank)[i];
        g_esrc[g_ptr[d.x] + r.x] = s.x;
        g_esrc[g_ptr[d.y] + r.y] = s.y;
        g_esrc[g_ptr[d.z] + r.z] = s.z;
        g_esrc[g_ptr[d.w] + r.w] = s.w;
    } else {
        for (; e < E; e++) g_esrc[g_ptr[dst[e]] + g_rank[e]] = src[e];
    }
}

// ---------------------------------------------------------------------------
// accumulate kernel: one warp per dst node, no atomics.
// ---------------------------------------------------------------------------
__device__ __forceinline__ float lr02(float x)  { return x > 0.f ? x : 0.2f  * x; }
__device__ __forceinline__ float lr001(float x) { return x > 0.f ? x : 0.01f * x; }

__global__ __launch_bounds__(256) void accum_kernel(
        const float* __restrict__ attn, float* __restrict__ out_ext,
        int to_internal, int N) {
    __shared__ float sat[D];
    if (threadIdx.x < D) sat[threadIdx.x] = attn[threadIdx.x];
    __syncthreads();

    int w = (blockIdx.x * blockDim.x + threadIdx.x) >> 5;
    int lane = threadIdx.x & 31;
    if (w >= N) return;  // warp-uniform

    int beg = g_ptr[w];
    int end = g_ptr[w + 1];

    float4 b0 = g_fd[w * 4 + 0], b1 = g_fd[w * 4 + 1];
    float4 b2 = g_fd[w * 4 + 2], b3 = g_fd[w * 4 + 3];
    float bb[D] = { b0.x, b0.y, b0.z, b0.w, b1.x, b1.y, b1.z, b1.w,
                    b2.x, b2.y, b2.z, b2.w, b3.x, b3.y, b3.z, b3.w };

    float acc[D];
#pragma unroll
    for (int j = 0; j < D; j++) acc[j] = 0.f;
    float den = 0.f;

    for (int i = beg + lane; i < end; i += 32) {
        int s = g_esrc[i];
        uint4 r0 = g_fsh[s * 2 + 0];
        uint4 r1 = g_fsh[s * 2 + 1];
        float a[D];
        {
            float2 f;
            f = __half22float2(*reinterpret_cast<__half2*>(&r0.x)); a[0]  = f.x; a[1]  = f.y;
            f = __half22float2(*reinterpret_cast<__half2*>(&r0.y)); a[2]  = f.x; a[3]  = f.y;
            f = __half22float2(*reinterpret_cast<__half2*>(&r0.z)); a[4]  = f.x; a[5]  = f.y;
            f = __half22float2(*reinterpret_cast<__half2*>(&r0.w)); a[6]  = f.x; a[7]  = f.y;
            f = __half22float2(*reinterpret_cast<__half2*>(&r1.x)); a[8]  = f.x; a[9]  = f.y;
            f = __half22float2(*reinterpret_cast<__half2*>(&r1.y)); a[10] = f.x; a[11] = f.y;
            f = __half22float2(*reinterpret_cast<__half2*>(&r1.z)); a[12] = f.x; a[13] = f.y;
            f = __half22float2(*reinterpret_cast<__half2*>(&r1.w)); a[14] = f.x; a[15] = f.y;
        }

        float sc = 0.f;
#pragma unroll
        for (int j = 0; j < D; j++) sc = fmaf(lr02(a[j] + bb[j]), sat[j], sc);

        float ex = __expf(sc);
        den += ex;
#pragma unroll
        for (int j = 0; j < D; j++) acc[j] = fmaf(ex, a[j], acc[j]);
    }

    // den: full butterfly
#pragma unroll
    for (int o = 16; o >= 1; o >>= 1) den += __shfl_xor_sync(0xffffffffu, den, o);

    // acc: multi-value exchange reduction. After all steps, even lane L holds
    // component ((L>>1)&15) of the full 32-lane sum in acc[0].
#pragma unroll
    for (int j = 0; j < 8; j++) {
        float send = (lane & 16) ? acc[j] : acc[j + 8];
        float recv = __shfl_xor_sync(0xffffffffu, send, 16);
        acc[j] = ((lane & 16) ? acc[j + 8] : acc[j]) + recv;
    }
#pragma unroll
    for (int j = 0; j < 4; j++) {
        float send = (lane & 8) ? acc[j] : acc[j + 4];
        float recv = __shfl_xor_sync(0xffffffffu, send, 8);
        acc[j] = ((lane & 8) ? acc[j + 4] : acc[j]) + recv;
    }
#pragma unroll
    for (int j = 0; j < 2; j++) {
        float send = (lane & 4) ? acc[j] : acc[j + 2];
        float recv = __shfl_xor_sync(0xffffffffu, send, 4);
        acc[j] = ((lane & 4) ? acc[j + 2] : acc[j]) + recv;
    }
    {
        float send = (lane & 2) ? acc[0] : acc[1];
        float recv = __shfl_xor_sync(0xffffffffu, send, 2);
        acc[0] = ((lane & 2) ? acc[1] : acc[0]) + recv;
    }
    acc[0] += __shfl_xor_sync(0xffffffffu, acc[0], 1);

    float inv = (den > 0.f) ? (1.0f / den) : 0.f;
    float* out = to_internal ? (float*)g_h2 : out_ext;
    if (!(lane & 1)) {
        float v = lr001(acc[0] * inv);
        out[w * D + ((lane >> 1) & 15)] = v;
    }
}

// ---------------------------------------------------------------------------
// launch
// ---------------------------------------------------------------------------
extern "C" void kernel_launch(void* const* d_in, const int* in_sizes, int n_in,
                              void* d_out, int out_size) {
    const float* emb  = (const float*)d_in[0];
    const int*   src1 = (const int*)d_in[1];
    const int*   dst1 = (const int*)d_in[2];
    const int*   src2 = (const int*)d_in[3];
    const int*   dst2 = (const int*)d_in[4];
    const float* Ws1  = (const float*)d_in[5];
    const float* bs1  = (const float*)d_in[6];
    const float* Wd1  = (const float*)d_in[7];
    const float* bd1  = (const float*)d_in[8];
    const float* at1  = (const float*)d_in[9];
    const float* Ws2  = (const float*)d_in[10];
    const float* bs2  = (const float*)d_in[11];
    const float* Wd2  = (const float*)d_in[12];
    const float* bd2  = (const float*)d_in[13];
    const float* at2  = (const float*)d_in[14];

    int N  = in_sizes[0] / D;
    int E1 = in_sizes[1];
    int E2 = in_sizes[3];

    int nbN  = (N + 255) / 256;
    int nbV1 = ((E1 + 3) / 4 + 255) / 256;     // 4 edges/thread
    int nbV2 = ((E2 + 3) / 4 + 255) / 256;
    int nbW  = (N + 7) / 8;                    // one warp per node
    int nbS  = (N + SCAN_BLK - 1) / SCAN_BLK;  // scan blocks (~196)

    // ---- Layer 1 ----
    feat_kernel<<<nbN, 256>>>(emb, 0, Ws1, bs1, Wd1, bd1, N);
    rank_kernel<<<nbV1, 256>>>(dst1, E1);
    scan1_kernel<<<nbS, SCAN_BLK>>>(N);
    scan2_kernel<<<1, 256>>>(nbS);
    scan3_kernel<<<nbS, SCAN_BLK>>>(N, E1);
    scatter_kernel<<<nbV1, 256>>>(src1, dst1, E1);
    accum_kernel<<<nbW, 256>>>(at1, nullptr, 1, N);

    // ---- Layer 2 ----
    feat_kernel<<<nbN, 256>>>(nullptr, 1, Ws2, bs2, Wd2, bd2, N);
    rank_kernel<<<nbV2, 256>>>(dst2, E2);
    scan1_kernel<<<nbS, SCAN_BLK>>>(N);
    scan2_kernel<<<1, 256>>>(nbS);
    scan3_kernel<<<nbS, SCAN_BLK>>>(N, E2);
    scatter_kernel<<<nbV2, 256>>>(src2, dst2, E2);
    accum_kernel<<<nbW, 256>>>(at2, (float*)d_out, 0, N);
}

// round 6
// speedup vs baseline: 2.7434x; 1.1523x over previous
#include <cuda_runtime.h>
#include <cuda_fp16.h>

#define D 16
#define NMAX 100000
#define EMAX 3400000
#define SCAN_BLK 512

// Scratch (static __device__). Referenced ONLY from device code.
__device__ uint4    g_fsh[NMAX * 2];   // layer-1 feat_src fp16 (32B/row)
__device__ float4   g_fd[NMAX * 4];    // layer-1 feat_dst fp32
__device__ uint4    g_fshB[NMAX * 2];  // layer-2 feat_src fp16 (written by accum1)
__device__ float4   g_fdB[NMAX * 4];   // layer-2 feat_dst fp32 (written by accum1)
__device__ int      g_cnt[NMAX];       // per-dst edge count
__device__ int      g_ptr[NMAX + 1];   // CSR row pointers
__device__ int      g_rank[EMAX];      // per-edge rank within dst bucket
__device__ int      g_esrc[EMAX];      // src index sorted by dst
__device__ unsigned g_state[1024];     // lookback scan state (flag<<30 | value)

__device__ __forceinline__ float lr02(float x)  { return x > 0.f ? x : 0.2f  * x; }
__device__ __forceinline__ float lr001(float x) { return x > 0.f ? x : 0.01f * x; }

// ---------------------------------------------------------------------------
// feat kernel (layer 1 only): fs1 = emb@Ws1+bs1 (fp16), fd1 = emb@Wd1+bd1 (fp32)
// Also zeroes histogram counters.
// ---------------------------------------------------------------------------
__global__ __launch_bounds__(256) void feat_kernel(
        const float* __restrict__ h,
        const float* __restrict__ Wsrc, const float* __restrict__ bsrc,
        const float* __restrict__ Wdst, const float* __restrict__ bdst,
        int N) {
    __shared__ float sWs[D * D], sWd[D * D], sbs[D], sbd[D];
    int tid = threadIdx.x;
    if (tid < D * D) { sWs[tid] = Wsrc[tid]; sWd[tid] = Wdst[tid]; }
    if (tid < D)     { sbs[tid] = bsrc[tid]; sbd[tid] = bdst[tid]; }
    __syncthreads();

    int n = blockIdx.x * blockDim.x + tid;
    if (n >= N) return;

    const float4* h4 = (const float4*)h + n * 4;
    float hr[D];
#pragma unroll
    for (int i = 0; i < 4; i++) {
        float4 v = h4[i];
        hr[4 * i + 0] = v.x; hr[4 * i + 1] = v.y; hr[4 * i + 2] = v.z; hr[4 * i + 3] = v.w;
    }
    float os[D], od[D];
#pragma unroll
    for (int j = 0; j < D; j++) { os[j] = sbs[j]; od[j] = sbd[j]; }
#pragma unroll
    for (int k = 0; k < D; k++) {
        float hv = hr[k];
#pragma unroll
        for (int j = 0; j < D; j++) {
            os[j] = fmaf(hv, sWs[k * D + j], os[j]);
            od[j] = fmaf(hv, sWd[k * D + j], od[j]);
        }
    }
    uint4 p0, p1;
    {
        __half2 t;
        t = __floats2half2_rn(os[0],  os[1]);  p0.x = *reinterpret_cast<unsigned*>(&t);
        t = __floats2half2_rn(os[2],  os[3]);  p0.y = *reinterpret_cast<unsigned*>(&t);
        t = __floats2half2_rn(os[4],  os[5]);  p0.z = *reinterpret_cast<unsigned*>(&t);
        t = __floats2half2_rn(os[6],  os[7]);  p0.w = *reinterpret_cast<unsigned*>(&t);
        t = __floats2half2_rn(os[8],  os[9]);  p1.x = *reinterpret_cast<unsigned*>(&t);
        t = __floats2half2_rn(os[10], os[11]); p1.y = *reinterpret_cast<unsigned*>(&t);
        t = __floats2half2_rn(os[12], os[13]); p1.z = *reinterpret_cast<unsigned*>(&t);
        t = __floats2half2_rn(os[14], os[15]); p1.w = *reinterpret_cast<unsigned*>(&t);
    }
    g_fsh[n * 2 + 0] = p0;
    g_fsh[n * 2 + 1] = p1;
#pragma unroll
    for (int i = 0; i < 4; i++)
        g_fd[n * 4 + i] = make_float4(od[4 * i], od[4 * i + 1], od[4 * i + 2], od[4 * i + 3]);
    g_cnt[n] = 0;
}

// ---------------------------------------------------------------------------
// rank: hist + per-edge rank via atomic return; also zeroes scan state
// ---------------------------------------------------------------------------
__global__ __launch_bounds__(256) void rank_kernel(const int* __restrict__ dst, int E) {
    if (blockIdx.x == 0) {
#pragma unroll
        for (int k = 0; k < 4; k++) g_state[threadIdx.x + 256 * k] = 0;
    }
    int i = blockIdx.x * blockDim.x + threadIdx.x;
    int e = i * 4;
    if (e + 3 < E) {
        int4 d = reinterpret_cast<const int4*>(dst)[i];
        int4 r;
        r.x = atomicAdd(&g_cnt[d.x], 1);
        r.y = atomicAdd(&g_cnt[d.y], 1);
        r.z = atomicAdd(&g_cnt[d.z], 1);
        r.w = atomicAdd(&g_cnt[d.w], 1);
        reinterpret_cast<int4*>(g_rank)[i] = r;
    } else {
        for (; e < E; e++) g_rank[e] = atomicAdd(&g_cnt[dst[e]], 1);
    }
}

// ---------------------------------------------------------------------------
// single-pass scan with decoupled lookback (all blocks co-resident)
// ---------------------------------------------------------------------------
__global__ __launch_bounds__(SCAN_BLK) void scan_kernel(int N, int E) {
    __shared__ int swarp[SCAN_BLK / 32];
    __shared__ unsigned sRun;
    int tid = threadIdx.x, lane = tid & 31, wid = tid >> 5;
    int bid = blockIdx.x;
    int i = bid * SCAN_BLK + tid;
    if (bid == 0 && tid == 0) g_ptr[N] = E;

    int v = (i < N) ? g_cnt[i] : 0;
    int x = v;
#pragma unroll
    for (int o = 1; o < 32; o <<= 1) {
        int y = __shfl_up_sync(0xffffffffu, x, o);
        if (lane >= o) x += y;
    }
    if (lane == 31) swarp[wid] = x;
    __syncthreads();
    if (wid == 0) {
        int s = (lane < SCAN_BLK / 32) ? swarp[lane] : 0;
#pragma unroll
        for (int o = 1; o < SCAN_BLK / 32; o <<= 1) {
            int y = __shfl_up_sync(0xffffffffu, s, o);
            if (lane >= o) s += y;
        }
        if (lane < SCAN_BLK / 32) swarp[lane] = s;
    }
    __syncthreads();
    int woff = wid ? swarp[wid - 1] : 0;
    int excl = x - v + woff;
    unsigned A = (unsigned)swarp[SCAN_BLK / 32 - 1];  // block aggregate

    if (wid == 0) {
        if (lane == 0) atomicExch(&g_state[bid], (1u << 30) | A);
        unsigned run = 0;
        int p = bid - 1;
        while (p >= 0) {
            int idx = p - lane;
            unsigned s;
            if (idx >= 0) {
                volatile unsigned* ps = (volatile unsigned*)&g_state[idx];
                do { s = *ps; } while ((s >> 30) == 0);
            } else {
                s = (2u << 30);  // virtual prefix 0 before block 0
            }
            unsigned flag = s >> 30;
            unsigned val = s & 0x3FFFFFFFu;
            unsigned pm = __ballot_sync(0xffffffffu, flag >= 2);
            int fp_ = pm ? (__ffs(pm) - 1) : 32;
            unsigned c = (lane <= fp_) ? val : 0;
#pragma unroll
            for (int o = 16; o >= 1; o >>= 1) c += __shfl_xor_sync(0xffffffffu, c, o);
            run += c;
            if (pm) break;
            p -= 32;
        }
        if (lane == 0) {
            atomicExch(&g_state[bid], (2u << 30) | ((run + A) & 0x3FFFFFFFu));
            sRun = run;
        }
    }
    __syncthreads();
    if (i < N) g_ptr[i] = excl + (int)sRun;
}

// ---------------------------------------------------------------------------
// scatter: pos = ptr[dst] + rank (no atomics)
// ---------------------------------------------------------------------------
__global__ __launch_bounds__(256) void scatter_kernel(
        const int* __restrict__ src, const int* __restrict__ dst, int E) {
    int i = blockIdx.x * blockDim.x + threadIdx.x;
    int e = i * 4;
    if (e + 3 < E) {
        int4 s = reinterpret_cast<const int4*>(src)[i];
        int4 d = reinterpret_cast<const int4*>(dst)[i];
        int4 r = reinterpret_cast<const int4*>(g_rank)[i];
        g_esrc[g_ptr[d.x] + r.x] = s.x;
        g_esrc[g_ptr[d.y] + r.y] = s.y;
        g_esrc[g_ptr[d.z] + r.z] = s.z;
        g_esrc[g_ptr[d.w] + r.w] = s.w;
    } else {
        for (; e < E; e++) g_esrc[g_ptr[dst[e]] + g_rank[e]] = src[e];
    }
}

// ---------------------------------------------------------------------------
// Shared accumulate body: half-warp (16 lanes) per node. After the reduction,
// lane L holds component (L&15) of its node's pre-activation sum in acc0.
// ---------------------------------------------------------------------------
#define ACCUM_BODY(FS_TABLE, FD_TABLE)                                         \
    int gw = (blockIdx.x * 256 + threadIdx.x) >> 5;                            \
    int lane = threadIdx.x & 31;                                               \
    int sub = lane & 15;                                                       \
    int node = gw * 2 + (lane >> 4);                                           \
    int beg = 0, end = 0;                                                      \
    if (node < N) { beg = g_ptr[node]; end = g_ptr[node + 1]; }                \
    int it = (end - beg + 15) >> 4;                                            \
    _Pragma("unroll")                                                          \
    for (int o = 16; o >= 1; o >>= 1)                                          \
        it = max(it, __shfl_xor_sync(0xffffffffu, it, o));                     \
    float bb[D];                                                               \
    if (node < N) {                                                            \
        const float4* f4 = FD_TABLE + node * 4;                                \
        _Pragma("unroll")                                                      \
        for (int q = 0; q < 4; q++) {                                          \
            float4 vq = f4[q];                                                 \
            bb[4*q+0] = vq.x; bb[4*q+1] = vq.y; bb[4*q+2] = vq.z; bb[4*q+3] = vq.w; \
        }                                                                      \
    } else {                                                                   \
        _Pragma("unroll")                                                      \
        for (int j = 0; j < D; j++) bb[j] = 0.f;                               \
    }                                                                          \
    float acc[D];                                                              \
    _Pragma("unroll")                                                          \
    for (int j = 0; j < D; j++) acc[j] = 0.f;                                  \
    float den = 0.f;                                                           \
    for (int i2 = 0; i2 < it; i2++) {                                          \
        int idx = beg + sub + i2 * 16;                                         \
        if (idx < end) {                                                       \
            int s = g_esrc[idx];                                               \
            uint4 r0 = FS_TABLE[s * 2 + 0];                                    \
            uint4 r1 = FS_TABLE[s * 2 + 1];                                    \
            float a[D];                                                        \
            float2 f;                                                          \
            f = __half22float2(*reinterpret_cast<__half2*>(&r0.x)); a[0]=f.x; a[1]=f.y;   \
            f = __half22float2(*reinterpret_cast<__half2*>(&r0.y)); a[2]=f.x; a[3]=f.y;   \
            f = __half22float2(*reinterpret_cast<__half2*>(&r0.z)); a[4]=f.x; a[5]=f.y;   \
            f = __half22float2(*reinterpret_cast<__half2*>(&r0.w)); a[6]=f.x; a[7]=f.y;   \
            f = __half22float2(*reinterpret_cast<__half2*>(&r1.x)); a[8]=f.x; a[9]=f.y;   \
            f = __half22float2(*reinterpret_cast<__half2*>(&r1.y)); a[10]=f.x; a[11]=f.y; \
            f = __half22float2(*reinterpret_cast<__half2*>(&r1.z)); a[12]=f.x; a[13]=f.y; \
            f = __half22float2(*reinterpret_cast<__half2*>(&r1.w)); a[14]=f.x; a[15]=f.y; \
            float sc = 0.f;                                                    \
            _Pragma("unroll")                                                  \
            for (int j = 0; j < D; j++) sc = fmaf(lr02(a[j] + bb[j]), sat[j], sc); \
            float ex = __expf(sc);                                             \
            den += ex;                                                         \
            _Pragma("unroll")                                                  \
            for (int j = 0; j < D; j++) acc[j] = fmaf(ex, a[j], acc[j]);       \
        }                                                                      \
    }                                                                          \
    _Pragma("unroll")                                                          \
    for (int o = 8; o >= 1; o >>= 1) den += __shfl_xor_sync(0xffffffffu, den, o); \
    _Pragma("unroll")                                                          \
    for (int j = 0; j < 8; j++) {                                              \
        float send = (lane & 8) ? acc[j] : acc[j + 8];                         \
        float recv = __shfl_xor_sync(0xffffffffu, send, 8);                    \
        acc[j] = ((lane & 8) ? acc[j + 8] : acc[j]) + recv;                    \
    }                                                                          \
    _Pragma("unroll")                                                          \
    for (int j = 0; j < 4; j++) {                                              \
        float send = (lane & 4) ? acc[j] : acc[j + 4];                         \
        float recv = __shfl_xor_sync(0xffffffffu, send, 4);                    \
        acc[j] = ((lane & 4) ? acc[j + 4] : acc[j]) + recv;                    \
    }                                                                          \
    _Pragma("unroll")                                                          \
    for (int j = 0; j < 2; j++) {                                              \
        float send = (lane & 2) ? acc[j] : acc[j + 2];                         \
        float recv = __shfl_xor_sync(0xffffffffu, send, 2);                    \
        acc[j] = ((lane & 2) ? acc[j + 2] : acc[j]) + recv;                    \
    }                                                                          \
    {                                                                          \
        float send = (lane & 1) ? acc[0] : acc[1];                             \
        float recv = __shfl_xor_sync(0xffffffffu, send, 1);                    \
        acc[0] = ((lane & 1) ? acc[1] : acc[0]) + recv;                        \
    }                                                                          \
    float inv = (den > 0.f) ? (1.0f / den) : 0.f;                              \
    float val = lr001(acc[0] * inv);

// layer-1 accumulate, fused with layer-2 feature projection.
// Writes fs2 (fp16) / fd2 (fp32) into the B buffers; zeroes g_cnt for rank-2.
__global__ __launch_bounds__(256) void accum1_kernel(
        const float* __restrict__ attn,
        const float* __restrict__ Ws2, const float* __restrict__ bs2,
        const float* __restrict__ Wd2, const float* __restrict__ bd2,
        int N) {
    __shared__ float sat[D];
    __shared__ float sWs[D * D], sWd[D * D], sbs[D], sbd[D];
    if (threadIdx.x < D) {
        sat[threadIdx.x] = attn[threadIdx.x];
        sbs[threadIdx.x] = bs2[threadIdx.x];
        sbd[threadIdx.x] = bd2[threadIdx.x];
    }
    if (threadIdx.x < D * D) { sWs[threadIdx.x] = Ws2[threadIdx.x]; sWd[threadIdx.x] = Wd2[threadIdx.x]; }
    __syncthreads();

    ACCUM_BODY(g_fsh, g_fd)

    // fused layer-2 projection: half-warp holds h2 row across its 16 lanes
    float os = sbs[sub], od = sbd[sub];
#pragma unroll
    for (int k = 0; k < D; k++) {
        float h2k = __shfl_sync(0xffffffffu, val, (lane & 16) + k);
        os = fmaf(h2k, sWs[k * D + sub], os);
        od = fmaf(h2k, sWd[k * D + sub], od);
    }
    float osn = __shfl_xor_sync(0xffffffffu, os, 1);
    if (node < N) {
        if (!(sub & 1)) {
            __half2 t = __floats2half2_rn(os, osn);
            reinterpret_cast<unsigned*>(g_fshB)[node * 8 + (sub >> 1)] = *reinterpret_cast<unsigned*>(&t);
        }
        reinterpret_cast<float*>(g_fdB)[node * D + sub] = od;
        if (sub == 0) g_cnt[node] = 0;
    }
}

// layer-2 accumulate: writes final output
__global__ __launch_bounds__(256) void accum2_kernel(
        const float* __restrict__ attn, float* __restrict__ out, int N) {
    __shared__ float sat[D];
    if (threadIdx.x < D) sat[threadIdx.x] = attn[threadIdx.x];
    __syncthreads();

    ACCUM_BODY(g_fshB, g_fdB)

    if (node < N) out[node * D + sub] = val;
}

// ---------------------------------------------------------------------------
// launch
// ---------------------------------------------------------------------------
extern "C" void kernel_launch(void* const* d_in, const int* in_sizes, int n_in,
                              void* d_out, int out_size) {
    const float* emb  = (const float*)d_in[0];
    const int*   src1 = (const int*)d_in[1];
    const int*   dst1 = (const int*)d_in[2];
    const int*   src2 = (const int*)d_in[3];
    const int*   dst2 = (const int*)d_in[4];
    const float* Ws1  = (const float*)d_in[5];
    const float* bs1  = (const float*)d_in[6];
    const float* Wd1  = (const float*)d_in[7];
    const float* bd1  = (const float*)d_in[8];
    const float* at1  = (const float*)d_in[9];
    const float* Ws2  = (const float*)d_in[10];
    const float* bs2  = (const float*)d_in[11];
    const float* Wd2  = (const float*)d_in[12];
    const float* bd2  = (const float*)d_in[13];
    const float* at2  = (const float*)d_in[14];

    int N  = in_sizes[0] / D;
    int E1 = in_sizes[1];
    int E2 = in_sizes[3];

    int nbN  = (N + 255) / 256;
    int nbV1 = ((E1 + 3) / 4 + 255) / 256;     // 4 edges/thread
    int nbV2 = ((E2 + 3) / 4 + 255) / 256;
    int nbA  = (N + 15) / 16;                  // 2 nodes per warp, 8 warps/block
    int nbS  = (N + SCAN_BLK - 1) / SCAN_BLK;  // ~196 blocks (all co-resident)

    // ---- Layer 1 ----
    feat_kernel<<<nbN, 256>>>(emb, Ws1, bs1, Wd1, bd1, N);
    rank_kernel<<<nbV1, 256>>>(dst1, E1);
    scan_kernel<<<nbS, SCAN_BLK>>>(N, E1);
    scatter_kernel<<<nbV1, 256>>>(src1, dst1, E1);
    accum1_kernel<<<nbA, 256>>>(at1, Ws2, bs2, Wd2, bd2, N);

    // ---- Layer 2 ----
    rank_kernel<<<nbV2, 256>>>(dst2, E2);
    scan_kernel<<<nbS, SCAN_BLK>>>(N, E2);
    scatter_kernel<<<nbV2, 256>>>(src2, dst2, E2);
    accum2_kernel<<<nbA, 256>>>(at2, (float*)d_out, N);
}